// round 1
// baseline (speedup 1.0000x reference)
#include <cuda_runtime.h>
#include <cuda_bf16.h>

// Problem constants
constexpr int SEQ   = 1024;
constexpr int BATCH = 8;
constexpr int DM    = 1024;
constexpr int NH    = 16;
constexpr int HD    = 64;     // DM / NH
constexpr int FF    = 4096;
constexpr int SB    = SEQ * BATCH;   // 8192 rows
constexpr float EPS = 1e-5f;

// ---------------------------------------------------------------------------
// Scratch (device globals — no allocation allowed)
// ---------------------------------------------------------------------------
__device__ float g_qkv[(size_t)SB * 3 * DM];              //  96 MB  [S*B, 3D]
__device__ float g_scores[(size_t)BATCH * NH * SEQ * SEQ];// 536 MB  [b,h,s,t]
__device__ float g_ctx[(size_t)SB * DM];                  //  32 MB  [S,B,D]
__device__ float g_x[(size_t)SB * DM];                    //  32 MB  post-LN1
__device__ float g_h1[(size_t)SB * FF];                   // 128 MB  FFN hidden
__device__ float g_tmp[(size_t)SB * DM];                  //  32 MB  pre-LN scratch

// ---------------------------------------------------------------------------
// Generic tiled GEMM:  C[m,n] = scale * sum_k A[m,k] * B(.,.)  (+bias)(+resid)(relu)
//   B_KN == false : B is [N, K] row-major (weights, "W^T" GEMM) — both K-contig
//   B_KN == true  : B is [K, N] row-major (attn @ V)
// Optional batching over blockIdx.z with (b, h) decomposition (Hdim > 0).
// ---------------------------------------------------------------------------
template<int BM, int BN, int BK, int TM, int TN, bool B_KN>
__global__ __launch_bounds__((BM/TM)*(BN/TN))
void gemm_kernel(const float* __restrict__ A, int lda, long sAb, long sAh,
                 const float* __restrict__ Bp, int ldb, long sBb, long sBh,
                 const float* __restrict__ bias,
                 const float* __restrict__ resid, int ldr,
                 float* __restrict__ C, int ldc, long sCb, long sCh,
                 int K, float scale, int do_relu, int Hdim)
{
    __shared__ __align__(16) float As[BK][BM];
    __shared__ __align__(16) float Bs[BK][BN];

    if (Hdim > 0) {
        int z  = blockIdx.z;
        int bb = z / Hdim;
        int hh = z % Hdim;
        A  += bb * sAb + hh * sAh;
        Bp += bb * sBb + hh * sBh;
        C  += bb * sCb + hh * sCh;
    }

    const int m0  = blockIdx.y * BM;
    const int n0  = blockIdx.x * BN;
    const int tid = threadIdx.x;
    constexpr int NT = (BM/TM) * (BN/TN);
    const int tx = tid % (BN / TN);
    const int ty = tid / (BN / TN);

    float acc[TM][TN];
#pragma unroll
    for (int i = 0; i < TM; i++)
#pragma unroll
        for (int j = 0; j < TN; j++) acc[i][j] = 0.f;

    constexpr int KV4 = BK / 4;         // float4 per K-row chunk
    constexpr int AV4 = BM * KV4;       // float4 loads for A tile

    for (int k0 = 0; k0 < K; k0 += BK) {
        // --- load A tile [BM x BK], transpose into As[BK][BM] ---
#pragma unroll
        for (int f = tid; f < AV4; f += NT) {
            int row = f / KV4;
            int cv  = f % KV4;
            float4 v = *reinterpret_cast<const float4*>(
                &A[(long)(m0 + row) * lda + k0 + cv * 4]);
            As[cv*4+0][row] = v.x;
            As[cv*4+1][row] = v.y;
            As[cv*4+2][row] = v.z;
            As[cv*4+3][row] = v.w;
        }
        // --- load B tile ---
        if constexpr (!B_KN) {
            constexpr int BV4 = BN * KV4;
#pragma unroll
            for (int f = tid; f < BV4; f += NT) {
                int row = f / KV4;
                int cv  = f % KV4;
                float4 v = *reinterpret_cast<const float4*>(
                    &Bp[(long)(n0 + row) * ldb + k0 + cv * 4]);
                Bs[cv*4+0][row] = v.x;
                Bs[cv*4+1][row] = v.y;
                Bs[cv*4+2][row] = v.z;
                Bs[cv*4+3][row] = v.w;
            }
        } else {
            constexpr int NV4 = BN / 4;
#pragma unroll
            for (int f = tid; f < BK * NV4; f += NT) {
                int row = f / NV4;   // k within tile
                int cv  = f % NV4;
                float4 v = *reinterpret_cast<const float4*>(
                    &Bp[(long)(k0 + row) * ldb + n0 + cv * 4]);
                *reinterpret_cast<float4*>(&Bs[row][cv * 4]) = v;
            }
        }
        __syncthreads();

#pragma unroll
        for (int kk = 0; kk < BK; kk++) {
            float a[TM], b[TN];
#pragma unroll
            for (int i = 0; i < TM; i++) a[i] = As[kk][ty * TM + i];
#pragma unroll
            for (int j = 0; j < TN; j++) b[j] = Bs[kk][tx * TN + j];
#pragma unroll
            for (int i = 0; i < TM; i++)
#pragma unroll
                for (int j = 0; j < TN; j++)
                    acc[i][j] = fmaf(a[i], b[j], acc[i][j]);
        }
        __syncthreads();
    }

    // --- epilogue ---
#pragma unroll
    for (int i = 0; i < TM; i++) {
        int m = m0 + ty * TM + i;
#pragma unroll
        for (int j = 0; j < TN; j++) {
            int n = n0 + tx * TN + j;
            float v = acc[i][j] * scale;
            if (bias)  v += bias[n];
            if (resid) v += resid[(long)m * ldr + n];
            if (do_relu) v = fmaxf(v, 0.f);
            C[(long)m * ldc + n] = v;
        }
    }
}

// ---------------------------------------------------------------------------
// Row softmax over last dim (1024), in place. One block (256 thr) per row.
// ---------------------------------------------------------------------------
__global__ void softmax_kernel(float* __restrict__ sc)
{
    __shared__ float red[8];
    const long row = blockIdx.x;
    float* p = sc + row * (long)SEQ;
    const int tid = threadIdx.x;

    float4 x = reinterpret_cast<float4*>(p)[tid];
    float m = fmaxf(fmaxf(x.x, x.y), fmaxf(x.z, x.w));
#pragma unroll
    for (int o = 16; o > 0; o >>= 1) m = fmaxf(m, __shfl_xor_sync(~0u, m, o));
    if ((tid & 31) == 0) red[tid >> 5] = m;
    __syncthreads();
    float mm = red[0];
#pragma unroll
    for (int i = 1; i < 8; i++) mm = fmaxf(mm, red[i]);

    float e0 = __expf(x.x - mm), e1 = __expf(x.y - mm);
    float e2 = __expf(x.z - mm), e3 = __expf(x.w - mm);
    float s = e0 + e1 + e2 + e3;
#pragma unroll
    for (int o = 16; o > 0; o >>= 1) s += __shfl_xor_sync(~0u, s, o);
    __syncthreads();
    if ((tid & 31) == 0) red[tid >> 5] = s;
    __syncthreads();
    float ss = 0.f;
#pragma unroll
    for (int i = 0; i < 8; i++) ss += red[i];
    float inv = 1.f / ss;
    x.x = e0 * inv; x.y = e1 * inv; x.z = e2 * inv; x.w = e3 * inv;
    reinterpret_cast<float4*>(p)[tid] = x;
}

// ---------------------------------------------------------------------------
// LayerNorm over last dim (1024). One block (256 thr) per row.
// ---------------------------------------------------------------------------
__global__ void layernorm_kernel(const float* __restrict__ in,
                                 const float* __restrict__ g,
                                 const float* __restrict__ b,
                                 float* __restrict__ out)
{
    __shared__ float rs[8], rq[8];
    const long row = blockIdx.x;
    const int tid = threadIdx.x;
    float4 x = reinterpret_cast<const float4*>(in + row * (long)DM)[tid];

    float s = x.x + x.y + x.z + x.w;
    float q = x.x*x.x + x.y*x.y + x.z*x.z + x.w*x.w;
#pragma unroll
    for (int o = 16; o > 0; o >>= 1) {
        s += __shfl_xor_sync(~0u, s, o);
        q += __shfl_xor_sync(~0u, q, o);
    }
    if ((tid & 31) == 0) { rs[tid >> 5] = s; rq[tid >> 5] = q; }
    __syncthreads();
    float ts = 0.f, tq = 0.f;
#pragma unroll
    for (int i = 0; i < 8; i++) { ts += rs[i]; tq += rq[i]; }

    const float mu  = ts * (1.f / DM);
    const float var = tq * (1.f / DM) - mu * mu;
    const float r   = rsqrtf(var + EPS);

    float4 gg = reinterpret_cast<const float4*>(g)[tid];
    float4 bb = reinterpret_cast<const float4*>(b)[tid];
    float4 y;
    y.x = (x.x - mu) * r * gg.x + bb.x;
    y.y = (x.y - mu) * r * gg.y + bb.y;
    y.z = (x.z - mu) * r * gg.z + bb.z;
    y.w = (x.w - mu) * r * gg.w + bb.w;
    reinterpret_cast<float4*>(out + row * (long)DM)[tid] = y;
}

// ---------------------------------------------------------------------------
// Host launch
// ---------------------------------------------------------------------------
extern "C" void kernel_launch(void* const* d_in, const int* in_sizes, int n_in,
                              void* d_out, int out_size)
{
    (void)in_sizes; (void)n_in; (void)out_size;
    const float* src       = (const float*)d_in[0];
    const float* in_proj_w = (const float*)d_in[1];
    const float* in_proj_b = (const float*)d_in[2];
    const float* out_w     = (const float*)d_in[3];
    const float* out_b     = (const float*)d_in[4];
    const float* w1        = (const float*)d_in[5];
    const float* b1        = (const float*)d_in[6];
    const float* w2        = (const float*)d_in[7];
    const float* b2        = (const float*)d_in[8];
    const float* g1        = (const float*)d_in[9];
    const float* be1       = (const float*)d_in[10];
    const float* g2        = (const float*)d_in[11];
    const float* be2       = (const float*)d_in[12];
    float* out = (float*)d_out;

    void *vp;
    float *p_qkv, *p_scores, *p_ctx, *p_x, *p_h1, *p_tmp;
    cudaGetSymbolAddress(&vp, g_qkv);    p_qkv    = (float*)vp;
    cudaGetSymbolAddress(&vp, g_scores); p_scores = (float*)vp;
    cudaGetSymbolAddress(&vp, g_ctx);    p_ctx    = (float*)vp;
    cudaGetSymbolAddress(&vp, g_x);      p_x      = (float*)vp;
    cudaGetSymbolAddress(&vp, g_h1);     p_h1     = (float*)vp;
    cudaGetSymbolAddress(&vp, g_tmp);    p_tmp    = (float*)vp;

    const int LDQKV = 3 * DM;           // 3072
    const int LDBIG = BATCH * 3 * DM;   // 24576, stride over s for q/k/v views

    // 1) QKV = src @ in_proj_w^T + in_proj_b   -> g_qkv [8192, 3072]
    {
        dim3 grid(3 * DM / 128, SB / 128, 1);
        gemm_kernel<128,128,16,8,8,false><<<grid, 256>>>(
            src, DM, 0, 0,
            in_proj_w, DM, 0, 0,
            in_proj_b, nullptr, 0,
            p_qkv, LDQKV, 0, 0,
            DM, 1.f, 0, 0);
    }

    // 2) scores[b,h,s,t] = scale * q[s] . k[t]   (batched over b*h = 128)
    {
        dim3 grid(SEQ / 128, SEQ / 128, BATCH * NH);
        gemm_kernel<128,128,16,8,8,false><<<grid, 256>>>(
            p_qkv,       LDBIG, (long)3 * DM, (long)HD,    // q view
            p_qkv + DM,  LDBIG, (long)3 * DM, (long)HD,    // k view
            nullptr, nullptr, 0,
            p_scores, SEQ, (long)NH * SEQ * SEQ, (long)SEQ * SEQ,
            HD, 0.125f /* 1/sqrt(64) */, 0, NH);
    }

    // 3) softmax over t
    softmax_kernel<<<BATCH * NH * SEQ, 256>>>(p_scores);

    // 4) ctx[s,b,h*64+d] = attn @ v   (batched, B is [K,N])
    {
        dim3 grid(1, SEQ / 128, BATCH * NH);
        gemm_kernel<128,64,16,8,4,true><<<grid, 256>>>(
            p_scores, SEQ, (long)NH * SEQ * SEQ, (long)SEQ * SEQ,
            p_qkv + 2 * DM, LDBIG, (long)3 * DM, (long)HD,  // v view
            nullptr, nullptr, 0,
            p_ctx, BATCH * DM, (long)DM, (long)HD,
            SEQ, 1.f, 0, NH);
    }

    // 5) tmp = ctx @ out_w^T + out_b + src
    {
        dim3 grid(DM / 128, SB / 128, 1);
        gemm_kernel<128,128,16,8,8,false><<<grid, 256>>>(
            p_ctx, DM, 0, 0,
            out_w, DM, 0, 0,
            out_b, src, DM,
            p_tmp, DM, 0, 0,
            DM, 1.f, 0, 0);
    }

    // 6) x = LN1(tmp)
    layernorm_kernel<<<SB, 256>>>(p_tmp, g1, be1, p_x);

    // 7) h1 = relu(x @ w1^T + b1)
    {
        dim3 grid(FF / 128, SB / 128, 1);
        gemm_kernel<128,128,16,8,8,false><<<grid, 256>>>(
            p_x, DM, 0, 0,
            w1, DM, 0, 0,
            b1, nullptr, 0,
            p_h1, FF, 0, 0,
            DM, 1.f, 1, 0);
    }

    // 8) tmp = h1 @ w2^T + b2 + x
    {
        dim3 grid(DM / 128, SB / 128, 1);
        gemm_kernel<128,128,16,8,8,false><<<grid, 256>>>(
            p_h1, FF, 0, 0,
            w2, FF, 0, 0,
            b2, p_x, DM,
            p_tmp, DM, 0, 0,
            FF, 1.f, 0, 0);
    }

    // 9) out = LN2(tmp)
    layernorm_kernel<<<SB, 256>>>(p_tmp, g2, be2, out);
}